// round 8
// baseline (speedup 1.0000x reference)
#include <cuda_runtime.h>
#include <cuda_bf16.h>
#include <cstdint>

// GRU_66314295050287 on GB300 (sm_103a) — R7: 4-buffer cp.async pipeline,
// prefetch depth 2, single barrier per chunk.
// x (32,2048,32,12) f32; M=65536 seqs of [FE=32][T=12] (1536 B each).
// Block = 64 threads = 64 seqs; 16 chunks of F=2 (24 floats = 6 float4/seq).

#define T_DIM        12
#define FE_DIM       32
#define SEQ_PER_BLK  64
#define NTHREADS     64
#define CHUNK_F      2
#define NCHUNKS      (FE_DIM / CHUNK_F)          // 16
#define CHUNK_FLOATS (CHUNK_F * T_DIM)           // 24
#define CHUNK_VEC4   (CHUNK_FLOATS / 4)          // 6 float4 per seq per chunk
#define SSTRIDE      (CHUNK_FLOATS + 4)          // 28 floats -> conflict-free LDS.128
#define NBUF         4
#define BUF_FLOATS   (SEQ_PER_BLK * SSTRIDE)     // 1792 floats per buffer
#define SEQ_VEC4     96                          // 1536 B per sequence

__device__ __forceinline__ float fast_sigmoid(float x) {
    return 1.0f / (1.0f + __expf(-x));
}
__device__ __forceinline__ float fast_tanh(float x) {
    float e = __expf(2.0f * x);
    return 1.0f - 2.0f / (1.0f + e);
}

__device__ __forceinline__ void cp_async16(unsigned int saddr, const void* gptr) {
    asm volatile("cp.async.cg.shared.global [%0], [%1], 16;\n" :: "r"(saddr), "l"(gptr));
}
__device__ __forceinline__ void cp_commit() {
    asm volatile("cp.async.commit_group;\n");
}
template <int N>
__device__ __forceinline__ void cp_wait() {
    asm volatile("cp.async.wait_group %0;\n" :: "n"(N));
}

extern __shared__ float smem[];

__global__ void __launch_bounds__(NTHREADS, 7)
gru_kernel(const float* __restrict__ x,
           const float* __restrict__ w_ih,   // [3][32]
           const float* __restrict__ w_hh,   // [3][1]
           const float* __restrict__ b_ih,   // [3]
           const float* __restrict__ b_hh,   // [3]
           const float* __restrict__ lin_w,  // [3][12]
           const float* __restrict__ lin_b,  // [3]
           float* __restrict__ out)          // [M][3]
{
    float* buf0  = smem;                        // NBUF x BUF_FLOATS
    float* s_wih = smem + NBUF * BUF_FLOATS;    // 96
    float* s_lw  = s_wih + 96;                  // 36

    const int tid = threadIdx.x;
#pragma unroll
    for (int i = tid; i < 96; i += NTHREADS) s_wih[i] = w_ih[i];
    if (tid < 36) s_lw[tid] = lin_w[tid];

    const int m0 = blockIdx.x * SEQ_PER_BLK;
    const float4* __restrict__ x4 = reinterpret_cast<const float4*>(x);

    const unsigned int sbase = (unsigned int)__cvta_generic_to_shared(buf0);

    // Issue one chunk's loads into buffer b: 64 seq * 6 float4 -> 6 per thread.
    auto issue_chunk = [&](int c, int b) {
#pragma unroll
        for (int k = 0; k < (SEQ_PER_BLK * CHUNK_VEC4) / NTHREADS; ++k) {
            int i  = k * NTHREADS + tid;
            int ms = i / CHUNK_VEC4;
            int q  = i - ms * CHUNK_VEC4;
            const void* g = (const void*)(x4 + (long)(m0 + ms) * SEQ_VEC4 + c * CHUNK_VEC4 + q);
            unsigned int s = sbase + (unsigned int)((b * BUF_FLOATS + ms * SSTRIDE + q * 4) * 4);
            cp_async16(s, g);
        }
        cp_commit();
    };

    const float bi0 = b_ih[0], bi1 = b_ih[1], bi2 = b_ih[2];
    float gx0[T_DIM], gx1[T_DIM], gx2[T_DIM];
#pragma unroll
    for (int t = 0; t < T_DIM; ++t) { gx0[t] = bi0; gx1[t] = bi1; gx2[t] = bi2; }

    issue_chunk(0, 0);
    issue_chunk(1, 1);

#pragma unroll
    for (int c = 0; c < NCHUNKS; ++c) {
        // Prefetch depth 2: fetch chunk c+2 into buffer (c+2)%4. Safe: that
        // buffer was last read at iteration c-2, and two __syncthreads have
        // intervened since every thread finished those reads.
        if (c + 2 < NCHUNKS) {
            issue_chunk(c + 2, (c + 2) & (NBUF - 1));
            cp_wait<2>();           // chunk c landed; c+1, c+2 in flight
        } else if (c + 1 < NCHUNKS) {
            cp_wait<1>();
        } else {
            cp_wait<0>();
        }
        __syncthreads();            // chunk c visible to all threads

        const float* my = buf0 + (c & (NBUF - 1)) * BUF_FLOATS + tid * SSTRIDE;
#pragma unroll
        for (int fl = 0; fl < CHUNK_F; ++fl) {
            int f = c * CHUNK_F + fl;
            float w0 = s_wih[f];
            float w1 = s_wih[32 + f];
            float w2 = s_wih[64 + f];
            float4 a = reinterpret_cast<const float4*>(my + fl * T_DIM)[0];
            float4 b = reinterpret_cast<const float4*>(my + fl * T_DIM)[1];
            float4 d = reinterpret_cast<const float4*>(my + fl * T_DIM)[2];
            float xt[T_DIM] = {a.x, a.y, a.z, a.w, b.x, b.y, b.z, b.w, d.x, d.y, d.z, d.w};
#pragma unroll
            for (int t = 0; t < T_DIM; ++t) {
                gx0[t] = fmaf(xt[t], w0, gx0[t]);
                gx1[t] = fmaf(xt[t], w1, gx1[t]);
                gx2[t] = fmaf(xt[t], w2, gx2[t]);
            }
        }
    }

    // Scalar-hidden GRU recurrence + relu + linear head.
    const float wh0 = w_hh[0], wh1 = w_hh[1], wh2 = w_hh[2];
    const float bh0 = b_hh[0], bh1 = b_hh[1], bh2 = b_hh[2];
    float o0 = lin_b[0], o1 = lin_b[1], o2 = lin_b[2];
    float h = 0.0f;
#pragma unroll
    for (int t = 0; t < T_DIM; ++t) {
        float r = fast_sigmoid(gx0[t] + wh0 * h + bh0);
        float z = fast_sigmoid(gx1[t] + wh1 * h + bh1);
        float n = fast_tanh(gx2[t] + r * (wh2 * h + bh2));
        h = (1.0f - z) * n + z * h;
        float hr = fmaxf(h, 0.0f);
        o0 = fmaf(hr, s_lw[t],       o0);
        o1 = fmaf(hr, s_lw[12 + t],  o1);
        o2 = fmaf(hr, s_lw[24 + t],  o2);
    }

    // Coalesced epilogue: stage [64][3] floats in smem, write 48 float4.
    __syncthreads();                // all reads of buf0 done before reuse
    float* s_out = buf0;
    s_out[tid * 3 + 0] = o0;        // stride 3 coprime with 32 -> conflict-free
    s_out[tid * 3 + 1] = o1;
    s_out[tid * 3 + 2] = o2;
    __syncthreads();
    if (tid < (SEQ_PER_BLK * 3) / 4) {
        reinterpret_cast<float4*>(out + (long)m0 * 3)[tid] =
            reinterpret_cast<const float4*>(s_out)[tid];
    }
}

extern "C" void kernel_launch(void* const* d_in, const int* in_sizes, int n_in,
                              void* d_out, int out_size) {
    const float* x     = (const float*)d_in[0];
    const float* w_ih  = (const float*)d_in[1];
    const float* w_hh  = (const float*)d_in[2];
    const float* b_ih  = (const float*)d_in[3];
    const float* b_hh  = (const float*)d_in[4];
    const float* lin_w = (const float*)d_in[5];
    const float* lin_b = (const float*)d_in[6];
    float* out = (float*)d_out;

    const int M = in_sizes[0] / (FE_DIM * T_DIM);   // 65536
    const int grid = M / SEQ_PER_BLK;               // 1024

    const size_t smem_bytes = (size_t)(NBUF * BUF_FLOATS + 96 + 36) * sizeof(float);
    cudaFuncSetAttribute(gru_kernel, cudaFuncAttributeMaxDynamicSharedMemorySize,
                         (int)smem_bytes);

    gru_kernel<<<grid, NTHREADS, smem_bytes>>>(x, w_ih, w_hh, b_ih, b_hh,
                                               lin_w, lin_b, out);
}

// round 9
// speedup vs baseline: 1.1216x; 1.1216x over previous
#include <cuda_runtime.h>
#include <cuda_bf16.h>
#include <cstdint>

// GRU_66314295050287 on GB300 (sm_103a) — R9: warp-sized blocks, fully
// independent per-warp cp.async pipelines (no multi-warp barriers anywhere).
// x (32,2048,32,12) f32; M=65536 seqs of [FE=32][T=12] (1536 B each).
// Block = 32 threads = 32 seqs; 8 chunks of F=4; double-buffered smem.
// ~14 co-resident blocks/SM -> 14 decoupled pipelines hiding DRAM latency.

#define T_DIM        12
#define FE_DIM       32
#define SEQ_PER_BLK  32
#define NTHREADS     32
#define CHUNK_F      4
#define NCHUNKS      (FE_DIM / CHUNK_F)          // 8
#define CHUNK_FLOATS (CHUNK_F * T_DIM)           // 48
#define CHUNK_VEC4   (CHUNK_FLOATS / 4)          // 12 float4 per seq per chunk
#define SSTRIDE      52                          // 52%32=20 -> 8 distinct bank-quads
#define NBUF         2
#define BUF_FLOATS   (SEQ_PER_BLK * SSTRIDE)     // 1664 floats per buffer
#define SEQ_VEC4     96                          // 1536 B per sequence

__device__ __forceinline__ float fast_sigmoid(float x) {
    return 1.0f / (1.0f + __expf(-x));
}
__device__ __forceinline__ float fast_tanh(float x) {
    float e = __expf(2.0f * x);
    return 1.0f - 2.0f / (1.0f + e);
}

__device__ __forceinline__ void cp_async16(unsigned int saddr, const void* gptr) {
    asm volatile("cp.async.cg.shared.global [%0], [%1], 16;\n" :: "r"(saddr), "l"(gptr));
}
__device__ __forceinline__ void cp_commit() {
    asm volatile("cp.async.commit_group;\n");
}
template <int N>
__device__ __forceinline__ void cp_wait() {
    asm volatile("cp.async.wait_group %0;\n" :: "n"(N));
}

extern __shared__ float smem[];

__global__ void __launch_bounds__(NTHREADS, 16)
gru_kernel(const float* __restrict__ x,
           const float* __restrict__ w_ih,   // [3][32]
           const float* __restrict__ w_hh,   // [3][1]
           const float* __restrict__ b_ih,   // [3]
           const float* __restrict__ b_hh,   // [3]
           const float* __restrict__ lin_w,  // [3][12]
           const float* __restrict__ lin_b,  // [3]
           float* __restrict__ out)          // [M][3]
{
    float* buf0  = smem;                        // NBUF x BUF_FLOATS
    float* s_wih = smem + NBUF * BUF_FLOATS;    // 96
    float* s_lw  = s_wih + 96;                  // 36

    const int tid = threadIdx.x;
#pragma unroll
    for (int i = tid; i < 96; i += NTHREADS) s_wih[i] = w_ih[i];
#pragma unroll
    for (int i = tid; i < 36; i += NTHREADS) s_lw[i] = lin_w[i];

    const int m0 = blockIdx.x * SEQ_PER_BLK;
    const float4* __restrict__ x4 = reinterpret_cast<const float4*>(x);

    const unsigned int sbase = (unsigned int)__cvta_generic_to_shared(buf0);

    // Issue one chunk's loads into buffer b: 32 seq * 12 float4 -> 12 per lane.
    // Consecutive lanes hit consecutive float4s (contiguous within each seq's
    // 192 B segment) -> near-fully coalesced; every touched line fully consumed.
    auto issue_chunk = [&](int c, int b) {
#pragma unroll
        for (int k = 0; k < (SEQ_PER_BLK * CHUNK_VEC4) / NTHREADS; ++k) {
            int i  = k * NTHREADS + tid;
            int ms = i / CHUNK_VEC4;
            int q  = i - ms * CHUNK_VEC4;
            const void* g = (const void*)(x4 + (long)(m0 + ms) * SEQ_VEC4 + c * CHUNK_VEC4 + q);
            unsigned int s = sbase + (unsigned int)((b * BUF_FLOATS + ms * SSTRIDE + q * 4) * 4);
            cp_async16(s, g);
        }
        cp_commit();
    };

    const float bi0 = b_ih[0], bi1 = b_ih[1], bi2 = b_ih[2];
    float gx0[T_DIM], gx1[T_DIM], gx2[T_DIM];
#pragma unroll
    for (int t = 0; t < T_DIM; ++t) { gx0[t] = bi0; gx1[t] = bi1; gx2[t] = bi2; }

    issue_chunk(0, 0);

#pragma unroll
    for (int c = 0; c < NCHUNKS; ++c) {
        // Buffer (c+1)&1 was fully read at iteration c-1 (barrier at end of
        // that iteration) -> safe to refill before waiting on chunk c.
        if (c + 1 < NCHUNKS) {
            issue_chunk(c + 1, (c + 1) & 1);
            cp_wait<1>();           // chunk c landed; c+1 in flight
        } else {
            cp_wait<0>();
        }
        __syncthreads();            // 1-warp block: 3-cycle BAR; chunk c visible

        const float* my = buf0 + (c & 1) * BUF_FLOATS + tid * SSTRIDE;
#pragma unroll
        for (int fl = 0; fl < CHUNK_F; ++fl) {
            int f = c * CHUNK_F + fl;
            float w0 = s_wih[f];
            float w1 = s_wih[32 + f];
            float w2 = s_wih[64 + f];
            float4 a = reinterpret_cast<const float4*>(my + fl * T_DIM)[0];
            float4 b = reinterpret_cast<const float4*>(my + fl * T_DIM)[1];
            float4 d = reinterpret_cast<const float4*>(my + fl * T_DIM)[2];
            float xt[T_DIM] = {a.x, a.y, a.z, a.w, b.x, b.y, b.z, b.w, d.x, d.y, d.z, d.w};
#pragma unroll
            for (int t = 0; t < T_DIM; ++t) {
                gx0[t] = fmaf(xt[t], w0, gx0[t]);
                gx1[t] = fmaf(xt[t], w1, gx1[t]);
                gx2[t] = fmaf(xt[t], w2, gx2[t]);
            }
        }
        __syncthreads();            // all lanes done with buffer c -> refillable
    }

    // Scalar-hidden GRU recurrence + relu + linear head.
    const float wh0 = w_hh[0], wh1 = w_hh[1], wh2 = w_hh[2];
    const float bh0 = b_hh[0], bh1 = b_hh[1], bh2 = b_hh[2];
    float o0 = lin_b[0], o1 = lin_b[1], o2 = lin_b[2];
    float h = 0.0f;
#pragma unroll
    for (int t = 0; t < T_DIM; ++t) {
        float r = fast_sigmoid(gx0[t] + wh0 * h + bh0);
        float z = fast_sigmoid(gx1[t] + wh1 * h + bh1);
        float n = fast_tanh(gx2[t] + r * (wh2 * h + bh2));
        h = (1.0f - z) * n + z * h;
        float hr = fmaxf(h, 0.0f);
        o0 = fmaf(hr, s_lw[t],       o0);
        o1 = fmaf(hr, s_lw[12 + t],  o1);
        o2 = fmaf(hr, s_lw[24 + t],  o2);
    }

    // Coalesced epilogue: stage [32][3] floats in smem, write 24 float4.
    float* s_out = buf0;            // reuse (barrier above covered final reads)
    s_out[tid * 3 + 0] = o0;        // stride 3 coprime with 32 -> conflict-free
    s_out[tid * 3 + 1] = o1;
    s_out[tid * 3 + 2] = o2;
    __syncthreads();
    if (tid < (SEQ_PER_BLK * 3) / 4) {
        reinterpret_cast<float4*>(out + (long)m0 * 3)[tid] =
            reinterpret_cast<const float4*>(s_out)[tid];
    }
}

extern "C" void kernel_launch(void* const* d_in, const int* in_sizes, int n_in,
                              void* d_out, int out_size) {
    const float* x     = (const float*)d_in[0];
    const float* w_ih  = (const float*)d_in[1];
    const float* w_hh  = (const float*)d_in[2];
    const float* b_ih  = (const float*)d_in[3];
    const float* b_hh  = (const float*)d_in[4];
    const float* lin_w = (const float*)d_in[5];
    const float* lin_b = (const float*)d_in[6];
    float* out = (float*)d_out;

    const int M = in_sizes[0] / (FE_DIM * T_DIM);   // 65536
    const int grid = M / SEQ_PER_BLK;               // 2048

    const size_t smem_bytes = (size_t)(NBUF * BUF_FLOATS + 96 + 36) * sizeof(float);
    cudaFuncSetAttribute(gru_kernel, cudaFuncAttributeMaxDynamicSharedMemorySize,
                         (int)smem_bytes);

    gru_kernel<<<grid, NTHREADS, smem_bytes>>>(x, w_ih, w_hh, b_ih, b_hh,
                                               lin_w, lin_b, out);
}